// round 7
// baseline (speedup 1.0000x reference)
#include <cuda_runtime.h>

namespace {
constexpr int T_  = 1024;
constexpr int S_  = 64;
constexpr int D_  = 256;
constexpr int TP_ = 8;
constexpr int C_  = 65;   // 2*H*N_K + 1
}

__device__ __forceinline__ unsigned pack_sgnabs(int v) {
    unsigned a = (unsigned)(v < 0 ? -v : v);
    return a | (v < 0 ? 0x80000000u : 0u);
}

__global__ __launch_bounds__(256, 4) void crit_main(
    const int*   __restrict__ sta_loc,
    const int*   __restrict__ nei_loc,
    const int*   __restrict__ rand_numbers,
    const float* __restrict__ sta_emb,
    const float* __restrict__ nei_emb,
    const float* __restrict__ mask,
    const float* __restrict__ rand_vals,
    const float* __restrict__ t_rand,
    float*       __restrict__ out)
{
    __shared__ float4   s_buf[2048];       // 32KB: rows 0..31 of NEXT tile's nei_emb
    __shared__ float    s_eu[S_];          // raw dot*rsqrt(nn); scaled by rns in C'
    __shared__ float    s_mask[S_];
    __shared__ float    s_cs[S_][TP_];
    __shared__ unsigned s_neiT[TP_][68];   // transposed, padded: (sign<<31)|abs
    __shared__ float    s_PT[TP_][68];     // sqrt(|eu|*mask) * B[s][p], transposed, padded
    __shared__ float    s_swc[68];         // sqrt(|eu|*mask)/128
    __shared__ unsigned s_cnc[C_][TP_];    // packed (sign<<31)|abs
    __shared__ float    s_loss[C_][TP_];   // unnormalized by lth (argmin-invariant)
    __shared__ float    s_red[8];
    __shared__ float    s_l32[2];
    __shared__ float    s_invlth;
    __shared__ float    s_rv[TP_];
    __shared__ float    s_rl[TP_];

    const int tid  = threadIdx.x;
    const int lane = tid & 31;
    const int warp = tid >> 5;
    const int p    = tid & 7;
    const int tb   = blockIdx.x * 2;       // two tiles per block

    // ---------------- Inline int64 detection (per-warp, no barrier) ----------------
    int dlo = sta_loc[2 * lane];
    int dhi = sta_loc[2 * lane + 1];
    unsigned bm = __ballot_sync(0xffffffffu, dhi == (dlo >> 31));
    const int str = (bm == 0xffffffffu) ? 2 : 1;

    #pragma unroll 1
    for (int ti = 0; ti < 2; ti++) {
        const int t = tb + ti;

        // ---------------- small per-tile loads ----------------
        float sv = sta_emb[(size_t)t * D_ + tid];
        if (tid < S_)  s_mask[tid] = mask[(size_t)t * S_ + tid];
        float tr = 0.f;
        if (tid < TP_) {
            s_rv[tid] = rand_vals[(size_t)t * TP_ + tid];
            tr        = t_rand[t];
        }
        int nb0 = nei_loc[((size_t)t * (S_*TP_) + tid) * str];
        int nb1 = nei_loc[((size_t)t * (S_*TP_) + 256 + tid) * str];
        int rn  = rand_numbers[((size_t)t * 256 + tid) * str];
        int sl  = sta_loc[((size_t)t * TP_ + p) * str];

        // ---------------- B: raw eu[s] = dot/|nei| ----------------
        if (ti == 1) {
            asm volatile("cp.async.wait_group 0;" ::: "memory");
            __syncthreads();               // all prefetch writes visible
        }
        {
            int q = lane & 7;
            const float4* sg4 = (const float4*)(sta_emb + (size_t)t * D_);
            #pragma unroll
            for (int it = 0; it < 2; it++) {
                int row = warp * 8 + it * 4 + (lane >> 3);
                float dot = 0.f, nn = 0.f;
                if (ti == 1 && warp < 4) {
                    // rows 0..31 from the prefetched smem buffer
                    const float4* nr = s_buf + row * 64;
                    #pragma unroll
                    for (int j = 0; j < 8; j++) {
                        float4 bb = nr[q + 8 * j];
                        float4 a  = sg4[q + 8 * j];
                        dot = fmaf(a.x, bb.x, dot); dot = fmaf(a.y, bb.y, dot);
                        dot = fmaf(a.z, bb.z, dot); dot = fmaf(a.w, bb.w, dot);
                        nn  = fmaf(bb.x, bb.x, nn); nn  = fmaf(bb.y, bb.y, nn);
                        nn  = fmaf(bb.z, bb.z, nn); nn  = fmaf(bb.w, bb.w, nn);
                    }
                } else {
                    const float4* nr = (const float4*)(nei_emb + ((size_t)t * S_ + row) * D_);
                    #pragma unroll
                    for (int j = 0; j < 8; j++) {
                        float4 bb = nr[q + 8 * j];
                        float4 a  = sg4[q + 8 * j];
                        dot = fmaf(a.x, bb.x, dot); dot = fmaf(a.y, bb.y, dot);
                        dot = fmaf(a.z, bb.z, dot); dot = fmaf(a.w, bb.w, dot);
                        nn  = fmaf(bb.x, bb.x, nn); nn  = fmaf(bb.y, bb.y, nn);
                        nn  = fmaf(bb.z, bb.z, nn); nn  = fmaf(bb.w, bb.w, nn);
                    }
                }
                #pragma unroll
                for (int o = 1; o < 8; o <<= 1) {
                    dot += __shfl_xor_sync(0xffffffffu, dot, o);
                    nn  += __shfl_xor_sync(0xffffffffu, nn,  o);
                }
                if (q == 0) s_eu[row] = dot * rsqrtf(nn);
            }
        }

        // ---------------- prefetch next tile's rows 0..31 (tile 0 only) ----------------
        // LDGSTS: no data registers; queued behind B's LDGs -> continuous DRAM stream.
        // Buffer is untouched during tile 0, so no read-write hazard.
        if (ti == 0) {
            const float4* src = (const float4*)(nei_emb + (size_t)(t + 1) * S_ * D_);
            unsigned base = (unsigned)__cvta_generic_to_shared(s_buf) + tid * 128u;
            #pragma unroll
            for (int k = 0; k < 8; k++) {
                asm volatile("cp.async.cg.shared.global [%0], [%1], 16;"
                             :: "r"(base + k * 16u), "l"(src + tid * 8 + k));
            }
            asm volatile("cp.async.commit_group;" ::: "memory");
        }

        // ---------------- D: cos_sn + packed nei ----------------
        {
            int aa = sl < 0 ? -sl : sl;
            #pragma unroll
            for (int it = 0; it < 2; it++) {
                int idx = tid + it * 256;
                int nb  = it ? nb1 : nb0;
                int s = idx >> 3;
                int sg = ((nb ^ sl) < 0);
                int na = nb < 0 ? -nb : nb;
                unsigned x = (unsigned)(na ^ aa) + 1u;
                int v  = __clz((int)x) - 16;
                int iv = sg ? -v : v;
                s_cs[s][p]   = (float)iv * 0.0625f;
                s_neiT[p][s] = (unsigned)na | (nb < 0 ? 0x80000000u : 0u);
            }
        }

        // ---------------- E: cnc packed ----------------
        {
            int k = tid >> 4, c = tid >> 3;   // c = 2k+j
            int r = sl ^ (1 << k) ^ (rn & ((1 << k) - 1));
            s_cnc[c][p]      = pack_sgnabs(r);
            s_cnc[c + 33][p] = pack_sgnabs(-r);
            if (tid < TP_) s_cnc[32][tid] = pack_sgnabs(sl);
        }

        // |sta|^2 partial reduce
        float ns = sv * sv;
        #pragma unroll
        for (int o = 16; o; o >>= 1) ns += __shfl_xor_sync(0xffffffffu, ns, o);
        if (lane == 0) s_red[warp] = ns;
        __syncthreads();                  // barrier 1

        // ---------------- invlth (warp 2, parallel with C') ----------------
        if (warp == 2) {
            float m = s_mask[lane] + s_mask[lane + 32];
            #pragma unroll
            for (int o = 16; o; o >>= 1) m += __shfl_xor_sync(0xffffffffu, m, o);
            if (lane == 0) s_invlth = 1.0f / (m + 1e-12f);
        }

        // ---------------- C' (warps 0-1): P = sqw*B, swc = sqw/128, loss32 ----------------
        if (tid < S_) {
            float tot = s_red[0] + s_red[1] + s_red[2] + s_red[3]
                      + s_red[4] + s_red[5] + s_red[6] + s_red[7];
            float rns = rsqrtf(tot);
            int s = tid;
            float4 ca = *(const float4*)&s_cs[s][0];
            float4 cb = *(const float4*)&s_cs[s][4];
            float sum = ca.x + ca.y + ca.z + ca.w + cb.x + cb.y + cb.z + cb.w;
            float eu  = s_eu[s] * rns;
            float w   = fabsf(eu) * s_mask[s];   // lth factored out (argmin-invariant)
            float sqw = sqrtf(w);
            s_swc[s]  = sqw * 0.0078125f;
            float cm  = fmaf(sum, 0.125f, -eu);  // sum/8 - eu
            float csv[8] = {ca.x, ca.y, ca.z, ca.w, cb.x, cb.y, cb.z, cb.w};
            #pragma unroll
            for (int pp = 0; pp < 8; pp++)
                s_PT[pp][s] = sqw * fmaf(csv[pp], -0.125f, cm);
            float t32 = w * cm * cm;
            #pragma unroll
            for (int o = 16; o; o >>= 1) t32 += __shfl_xor_sync(0xffffffffu, t32, o);
            if (lane == 0) s_l32[warp] = t32;
        }
        __syncthreads();                  // barrier 2

        // ---------------- F: loss[c][p] and loss[c+33][p] share the clz chain ----------------
        {
            int c0 = tid >> 3;             // 0..31
            unsigned ca0   = s_cnc[c0][p];
            unsigned ca1   = s_cnc[c0 + 33][p];
            unsigned sflip = (ca0 ^ ca1) & 0x80000000u;  // 0 iff r==0
            float acc0 = 0.f, acc1 = 0.f;
            const int4*   nt  = (const int4*)&s_neiT[p][0];
            const float4* ptv = (const float4*)&s_PT[p][0];
            const float4* swp = (const float4*)s_swc;
            #pragma unroll
            for (int s4 = 0; s4 < 16; s4++) {
                int4   nv = nt[s4];
                float4 Pv = ptv[s4];
                float4 sw = swp[s4];
                #pragma unroll
                for (int i = 0; i < 4; i++) {
                    unsigned ne = (i == 0) ? (unsigned)nv.x : (i == 1) ? (unsigned)nv.y
                                : (i == 2) ? (unsigned)nv.z : (unsigned)nv.w;
                    float P   = (i == 0) ? Pv.x : (i == 1) ? Pv.y : (i == 2) ? Pv.z : Pv.w;
                    float swv = (i == 0) ? sw.x : (i == 1) ? sw.y : (i == 2) ? sw.z : sw.w;
                    unsigned xr = ca0 ^ ne;
                    unsigned x1 = (xr & 0x1FFFFu) + 1u;
                    float uf = (float)(__clz((int)x1) - 16);
                    float us0 = __int_as_float(__float_as_int(uf) ^ (xr & 0x80000000u));
                    float us1 = __int_as_float(__float_as_int(us0) ^ sflip);
                    float h0 = fmaf(us0, swv, P);
                    float h1 = fmaf(us1, swv, P);
                    acc0 = fmaf(h0, h0, acc0);
                    acc1 = fmaf(h1, h1, acc1);
                }
            }
            s_loss[c0][p]      = acc0;
            s_loss[c0 + 33][p] = acc1;
            if (tid < TP_) s_loss[32][tid] = s_l32[0] + s_l32[1];
        }
        __syncthreads();                  // barrier 3

        // ---------------- G: argmin, selection, outputs ----------------
        if (tid < TP_) {
            float best = s_loss[0][tid]; int bc = 0;
            #pragma unroll
            for (int c = 1; c < C_; c++) {
                float v = s_loss[c][tid];
                if (v < best) { best = v; bc = c; }       // first-occurrence argmin
            }
            float rv = s_rv[tid]; int rank = 0;
            #pragma unroll
            for (int q = 0; q < 8; q++) {
                float o = s_rv[q];
                rank += (o < rv) || (o == rv && q < tid); // stable argsort rank
            }
            int selg = (tr < 0.8f);
            int ci = (rank < 4) ? (selg ? bc : 32) : 32;
            unsigned pk = s_cnc[ci][tid];
            int val = (pk & 0x80000000u) ? -(int)(pk & 0x7fffffffu) : (int)pk;
            out[(size_t)t * TP_ + tid] = (float)val;
            s_rl[tid] = s_loss[ci][tid];
            __syncwarp(0x000000ffu);
            if (tid == 0) {
                float rl = 0.f;
                #pragma unroll
                for (int q = 0; q < 8; q++) rl += s_rl[q];
                out[(size_t)T_ * TP_ + t] = rl * 0.125f * s_invlth;
            }
        }
        __syncthreads();                  // barrier 4: protect smem before next tile
    }
}

extern "C" void kernel_launch(void* const* d_in, const int* in_sizes, int n_in,
                              void* d_out, int out_size) {
    (void)in_sizes; (void)n_in; (void)out_size;
    const int*   sta_loc      = (const int*)  d_in[0];
    const int*   nei_loc      = (const int*)  d_in[1];
    const int*   rand_numbers = (const int*)  d_in[2];
    const float* sta_emb      = (const float*)d_in[3];
    const float* nei_emb      = (const float*)d_in[4];
    const float* mask         = (const float*)d_in[5];
    const float* rand_vals    = (const float*)d_in[6];
    const float* t_rand       = (const float*)d_in[7];
    float* out = (float*)d_out;

    crit_main<<<T_ / 2, 256>>>(sta_loc, nei_loc, rand_numbers,
                               sta_emb, nei_emb, mask, rand_vals, t_rand, out);
}

// round 8
// speedup vs baseline: 1.3088x; 1.3088x over previous
#include <cuda_runtime.h>

namespace {
constexpr int T_  = 1024;
constexpr int S_  = 64;
constexpr int D_  = 256;
constexpr int TP_ = 8;
constexpr int C_  = 65;   // 2*H*N_K + 1
}

__device__ __forceinline__ unsigned pack_sgnabs(int v) {
    unsigned a = (unsigned)(v < 0 ? -v : v);
    return a | (v < 0 ? 0x80000000u : 0u);
}

__global__ __launch_bounds__(128, 8) void crit_main(
    const int*   __restrict__ sta_loc,
    const int*   __restrict__ nei_loc,
    const int*   __restrict__ rand_numbers,
    const float* __restrict__ sta_emb,
    const float* __restrict__ nei_emb,
    const float* __restrict__ mask,
    const float* __restrict__ rand_vals,
    const float* __restrict__ t_rand,
    float*       __restrict__ out)
{
    __shared__ float    s_eu[S_];          // raw dot*rsqrt(nn); scaled by rns in C'
    __shared__ float    s_mask[S_];
    __shared__ float    s_cs[S_][TP_];
    __shared__ unsigned s_neiT[TP_][68];   // transposed, padded: (sign<<31)|abs
    __shared__ float    s_PT[TP_][68];     // sqrt(|eu|*mask) * B[s][p], transposed, padded
    __shared__ float    s_swc[68];         // sqrt(|eu|*mask)/128
    __shared__ unsigned s_cnc[C_][TP_];    // packed (sign<<31)|abs
    __shared__ float    s_loss[C_][TP_];   // unnormalized by lth (argmin-invariant)
    __shared__ float    s_red[4];
    __shared__ float    s_l32[2];
    __shared__ float    s_invlth;
    __shared__ float    s_rv[TP_];
    __shared__ float    s_rl[TP_];

    const int t    = blockIdx.x;
    const int tid  = threadIdx.x;          // 0..127
    const int lane = tid & 31;
    const int warp = tid >> 5;             // 0..3
    const int p    = tid & 7;

    // ---------------- Inline int64 detection (per-warp, no barrier) ----------------
    int dlo = sta_loc[2 * lane];
    int dhi = sta_loc[2 * lane + 1];
    unsigned bmll = __ballot_sync(0xffffffffu, dhi == (dlo >> 31));
    const int str = (bmll == 0xffffffffu) ? 2 : 1;

    // ---------------- small per-tile loads ----------------
    float sv0 = sta_emb[(size_t)t * D_ + tid];
    float sv1 = sta_emb[(size_t)t * D_ + 128 + tid];
    if (tid < S_)  s_mask[tid] = mask[(size_t)t * S_ + tid];
    float tr = 0.f;
    if (tid < TP_) {
        s_rv[tid] = rand_vals[(size_t)t * TP_ + tid];
        tr        = t_rand[t];
    }
    int nbv[4];
    #pragma unroll
    for (int it = 0; it < 4; it++)
        nbv[it] = nei_loc[((size_t)t * (S_*TP_) + it * 128 + tid) * str];
    int rn0 = rand_numbers[((size_t)t * 256 + tid) * str];
    int rn1 = rand_numbers[((size_t)t * 256 + 128 + tid) * str];
    int sl  = sta_loc[((size_t)t * TP_ + p) * str];

    // ---------------- B: raw eu[s] = dot/|nei|; 8 lanes/row, 16 rows/warp ----------------
    {
        int q = lane & 7;
        const float4* sg4 = (const float4*)(sta_emb + (size_t)t * D_);
        #pragma unroll
        for (int it = 0; it < 4; it++) {
            int row = warp * 16 + it * 4 + (lane >> 3);
            const float4* nr = (const float4*)(nei_emb + ((size_t)t * S_ + row) * D_);
            float dot = 0.f, nn = 0.f;
            #pragma unroll
            for (int j = 0; j < 8; j++) {
                float4 bb = nr[q + 8 * j];
                float4 a  = sg4[q + 8 * j];
                dot = fmaf(a.x, bb.x, dot); dot = fmaf(a.y, bb.y, dot);
                dot = fmaf(a.z, bb.z, dot); dot = fmaf(a.w, bb.w, dot);
                nn  = fmaf(bb.x, bb.x, nn); nn  = fmaf(bb.y, bb.y, nn);
                nn  = fmaf(bb.z, bb.z, nn); nn  = fmaf(bb.w, bb.w, nn);
            }
            #pragma unroll
            for (int o = 1; o < 8; o <<= 1) {
                dot += __shfl_xor_sync(0xffffffffu, dot, o);
                nn  += __shfl_xor_sync(0xffffffffu, nn,  o);
            }
            if (q == 0) s_eu[row] = dot * rsqrtf(nn);
        }
    }

    // ---------------- D: cos_sn + packed nei ----------------
    {
        int aa = sl < 0 ? -sl : sl;
        #pragma unroll
        for (int it = 0; it < 4; it++) {
            int idx = tid + it * 128;
            int nb  = nbv[it];
            int s = idx >> 3;
            int sg = ((nb ^ sl) < 0);
            int na = nb < 0 ? -nb : nb;
            unsigned x = (unsigned)(na ^ aa) + 1u;
            int v  = __clz((int)x) - 16;
            int iv = sg ? -v : v;
            s_cs[s][p]   = (float)iv * 0.0625f;
            s_neiT[p][s] = (unsigned)na | (nb < 0 ? 0x80000000u : 0u);
        }
    }

    // ---------------- E: cnc packed (2 items/thread) ----------------
    {
        int c = tid >> 3;                  // 0..15
        int k = tid >> 4;                  // 0..7
        int r0 = sl ^ (1 << k) ^ (rn0 & ((1 << k) - 1));
        s_cnc[c][p]      = pack_sgnabs(r0);
        s_cnc[c + 33][p] = pack_sgnabs(-r0);
        int k2 = k + 8;                    // 8..15
        int r1 = sl ^ (1 << k2) ^ (rn1 & ((1 << k2) - 1));
        s_cnc[c + 16][p] = pack_sgnabs(r1);
        s_cnc[c + 49][p] = pack_sgnabs(-r1);
        if (tid < TP_) s_cnc[32][tid] = pack_sgnabs(sl);
    }

    // |sta|^2 partial reduce
    float ns = fmaf(sv0, sv0, sv1 * sv1);
    #pragma unroll
    for (int o = 16; o; o >>= 1) ns += __shfl_xor_sync(0xffffffffu, ns, o);
    if (lane == 0) s_red[warp] = ns;
    __syncthreads();                      // barrier 1

    // ---------------- invlth (warp 2, parallel with C') ----------------
    if (warp == 2) {
        float m = s_mask[lane] + s_mask[lane + 32];
        #pragma unroll
        for (int o = 16; o; o >>= 1) m += __shfl_xor_sync(0xffffffffu, m, o);
        if (lane == 0) s_invlth = 1.0f / (m + 1e-12f);
    }

    // ---------------- C' (warps 0-1): P = sqw*B, swc = sqw/128, loss32 ----------------
    if (tid < S_) {
        float tot = s_red[0] + s_red[1] + s_red[2] + s_red[3];
        float rns = rsqrtf(tot);
        int s = tid;
        float4 ca = *(const float4*)&s_cs[s][0];
        float4 cb = *(const float4*)&s_cs[s][4];
        float sum = ca.x + ca.y + ca.z + ca.w + cb.x + cb.y + cb.z + cb.w;
        float eu  = s_eu[s] * rns;
        float w   = fabsf(eu) * s_mask[s];   // lth factored out (argmin-invariant)
        float sqw = sqrtf(w);
        s_swc[s]  = sqw * 0.0078125f;
        float cm  = fmaf(sum, 0.125f, -eu);  // sum/8 - eu
        float csv[8] = {ca.x, ca.y, ca.z, ca.w, cb.x, cb.y, cb.z, cb.w};
        #pragma unroll
        for (int pp = 0; pp < 8; pp++)
            s_PT[pp][s] = sqw * fmaf(csv[pp], -0.125f, cm);
        float t32 = w * cm * cm;
        #pragma unroll
        for (int o = 16; o; o >>= 1) t32 += __shfl_xor_sync(0xffffffffu, t32, o);
        if (lane == 0) s_l32[warp] = t32;
    }
    __syncthreads();                      // barrier 2

    // ---------------- F: 4 candidate chains per thread share each LDS ----------------
    {
        int c0 = tid >> 3;                 // 0..15
        unsigned caA0   = s_cnc[c0][p];
        unsigned caA1   = s_cnc[c0 + 33][p];
        unsigned sflipA = (caA0 ^ caA1) & 0x80000000u;
        unsigned caB0   = s_cnc[c0 + 16][p];
        unsigned caB1   = s_cnc[c0 + 49][p];
        unsigned sflipB = (caB0 ^ caB1) & 0x80000000u;
        float accA0 = 0.f, accA1 = 0.f, accB0 = 0.f, accB1 = 0.f;
        const int4*   nt  = (const int4*)&s_neiT[p][0];
        const float4* ptv = (const float4*)&s_PT[p][0];
        const float4* swp = (const float4*)s_swc;
        #pragma unroll
        for (int s4 = 0; s4 < 16; s4++) {
            int4   nv = nt[s4];
            float4 Pv = ptv[s4];
            float4 sw = swp[s4];
            #pragma unroll
            for (int i = 0; i < 4; i++) {
                unsigned ne = (i == 0) ? (unsigned)nv.x : (i == 1) ? (unsigned)nv.y
                            : (i == 2) ? (unsigned)nv.z : (unsigned)nv.w;
                float P   = (i == 0) ? Pv.x : (i == 1) ? Pv.y : (i == 2) ? Pv.z : Pv.w;
                float swv = (i == 0) ? sw.x : (i == 1) ? sw.y : (i == 2) ? sw.z : sw.w;
                // chain A (c0 / c0+33)
                {
                    unsigned xr = caA0 ^ ne;
                    unsigned x1 = (xr & 0x1FFFFu) + 1u;
                    float uf = (float)(__clz((int)x1) - 16);
                    float us0 = __int_as_float(__float_as_int(uf) ^ (xr & 0x80000000u));
                    float us1 = __int_as_float(__float_as_int(us0) ^ sflipA);
                    float h0 = fmaf(us0, swv, P);
                    float h1 = fmaf(us1, swv, P);
                    accA0 = fmaf(h0, h0, accA0);
                    accA1 = fmaf(h1, h1, accA1);
                }
                // chain B (c0+16 / c0+49)
                {
                    unsigned xr = caB0 ^ ne;
                    unsigned x1 = (xr & 0x1FFFFu) + 1u;
                    float uf = (float)(__clz((int)x1) - 16);
                    float us0 = __int_as_float(__float_as_int(uf) ^ (xr & 0x80000000u));
                    float us1 = __int_as_float(__float_as_int(us0) ^ sflipB);
                    float h0 = fmaf(us0, swv, P);
                    float h1 = fmaf(us1, swv, P);
                    accB0 = fmaf(h0, h0, accB0);
                    accB1 = fmaf(h1, h1, accB1);
                }
            }
        }
        s_loss[c0][p]      = accA0;
        s_loss[c0 + 33][p] = accA1;
        s_loss[c0 + 16][p] = accB0;
        s_loss[c0 + 49][p] = accB1;
        if (tid < TP_) s_loss[32][tid] = s_l32[0] + s_l32[1];
    }
    __syncthreads();                      // barrier 3

    // ---------------- G: argmin, selection, outputs ----------------
    if (tid < TP_) {
        float best = s_loss[0][tid]; int bc = 0;
        #pragma unroll
        for (int c = 1; c < C_; c++) {
            float v = s_loss[c][tid];
            if (v < best) { best = v; bc = c; }       // first-occurrence argmin
        }
        float rv = s_rv[tid]; int rank = 0;
        #pragma unroll
        for (int q = 0; q < 8; q++) {
            float o = s_rv[q];
            rank += (o < rv) || (o == rv && q < tid); // stable argsort rank
        }
        int selg = (tr < 0.8f);
        int ci = (rank < 4) ? (selg ? bc : 32) : 32;
        unsigned pk = s_cnc[ci][tid];
        int val = (pk & 0x80000000u) ? -(int)(pk & 0x7fffffffu) : (int)pk;
        out[(size_t)t * TP_ + tid] = (float)val;
        s_rl[tid] = s_loss[ci][tid];
        __syncwarp(0x000000ffu);
        if (tid == 0) {
            float rl = 0.f;
            #pragma unroll
            for (int q = 0; q < 8; q++) rl += s_rl[q];
            out[(size_t)T_ * TP_ + t] = rl * 0.125f * s_invlth;
        }
    }
}

extern "C" void kernel_launch(void* const* d_in, const int* in_sizes, int n_in,
                              void* d_out, int out_size) {
    (void)in_sizes; (void)n_in; (void)out_size;
    const int*   sta_loc      = (const int*)  d_in[0];
    const int*   nei_loc      = (const int*)  d_in[1];
    const int*   rand_numbers = (const int*)  d_in[2];
    const float* sta_emb      = (const float*)d_in[3];
    const float* nei_emb      = (const float*)d_in[4];
    const float* mask         = (const float*)d_in[5];
    const float* rand_vals    = (const float*)d_in[6];
    const float* t_rand       = (const float*)d_in[7];
    float* out = (float*)d_out;

    crit_main<<<T_, 128>>>(sta_loc, nei_loc, rand_numbers,
                           sta_emb, nei_emb, mask, rand_vals, t_rand, out);
}